// round 16
// baseline (speedup 1.0000x reference)
#include <cuda_runtime.h>
#include <cuda_bf16.h>

// pred (N,V,C,T,H,W) = (8,3,24,8,128,128); mask (N,H,W); vq (1,C)
#define N_ 8
#define V_ 3
#define C_ 24
#define T_ 8
#define HW_ 16384
#define SLICES_PER_N 576              // V*C*T
#define POS_PER_CTA 1024              // 256 threads * 4 floats
#define CHUNKS 16                     // HW_/POS_PER_CTA
#define GROUPS 24                     // slice groups per n
#define SLICES_PER_GROUP 24           // 576/24 = 3 c-values * T
#define NCTAS (N_ * CHUNKS * GROUPS)  // 3072
#define NWSUM (N_ * CHUNKS)           // 128

// Fixed scratch (no dynamic allocation allowed)
__device__ float g_partials[NCTAS];
__device__ float g_wsum[NWSUM];
__device__ unsigned int g_ticket = 0;

__device__ __forceinline__ float warp_sum(float v) {
    #pragma unroll
    for (int off = 16; off > 0; off >>= 1)
        v += __shfl_xor_sync(0xFFFFFFFFu, v, off);
    return v;
}

__global__ __launch_bounds__(256) void fused_loss_kernel(
    const float* __restrict__ pred,
    const int* __restrict__ mask,
    const float* __restrict__ vq,
    float* __restrict__ out)
{
    const int b = blockIdx.x;
    const int n = b / (CHUNKS * GROUPS);
    const int rem = b % (CHUNKS * GROUPS);
    const int chunk = rem / GROUPS;
    const int grp = rem % GROUPS;
    const int tid = threadIdx.x;
    const int lane = tid & 31;
    const int wid = tid >> 5;

    __shared__ float swarp[8];
    __shared__ unsigned int s_is_last;

    const int pos0 = chunk * POS_PER_CTA + tid * 4;

    // Load this thread's 4 mask weights ONCE; reused across all 24 slices.
    int4 m = *reinterpret_cast<const int4*>(mask + (size_t)n * HW_ + pos0);
    const float w0 = (float)(1 - m.x);
    const float w1 = (float)(1 - m.y);
    const float w2 = (float)(1 - m.z);
    const float w3 = (float)(1 - m.w);

    // Group-0 CTAs record the weight sum for this (n, chunk) — each mask
    // position counted exactly once across the whole grid.
    if (grp == 0) {
        float ws = warp_sum(w0 + w1 + w2 + w3);
        if (lane == 0) swarp[wid] = ws;
        __syncthreads();
        if (tid == 0) {
            float tot = 0.0f;
            #pragma unroll
            for (int i = 0; i < 8; i++) tot += swarp[i];
            g_wsum[n * CHUNKS + chunk] = tot;
        }
        __syncthreads();   // protect swarp reuse below
    }

    // Main loop: 24 slices of pred for this (n, chunk); weights stay in regs.
    const float* base = pred
        + ((size_t)n * SLICES_PER_N + (size_t)grp * SLICES_PER_GROUP) * HW_
        + pos0;

    float acc0 = 0.0f, acc1 = 0.0f;
    #pragma unroll
    for (int cc = 0; cc < 3; cc++) {
        const float vqc = vq[(grp * 3 + cc) % C_];
        #pragma unroll 4
        for (int t = 0; t < T_; t++) {
            float4 p = *reinterpret_cast<const float4*>(base + (size_t)(cc * T_ + t) * HW_);
            acc0 = fmaf(fabsf(p.x - vqc), w0, acc0);
            acc1 = fmaf(fabsf(p.y - vqc), w1, acc1);
            acc0 = fmaf(fabsf(p.z - vqc), w2, acc0);
            acc1 = fmaf(fabsf(p.w - vqc), w3, acc1);
        }
    }

    // Block reduction (fixed order -> deterministic)
    float acc = warp_sum(acc0 + acc1);
    if (lane == 0) swarp[wid] = acc;
    __syncthreads();
    if (wid == 0) {
        float v = (lane < 8) ? swarp[lane] : 0.0f;
        #pragma unroll
        for (int off = 4; off > 0; off >>= 1)
            v += __shfl_xor_sync(0xFFFFFFFFu, v, off);
        if (lane == 0) g_partials[b] = v;
    }

    // Last-CTA ticket: the final arriving CTA reduces everything.
    if (tid == 0) {
        __threadfence();
        unsigned int old = atomicAdd(&g_ticket, 1u);
        s_is_last = (old == NCTAS - 1) ? 1u : 0u;
    }
    __syncthreads();
    if (!s_is_last) return;

    // Final reduction: fixed-order double accumulation -> bit-deterministic.
    // __ldcg: force L2 reads (skip possibly-stale L1 lines for cross-CTA data).
    __shared__ double sdbl[256];
    double num = 0.0;
    for (int i = tid; i < NCTAS; i += 256) num += (double)__ldcg(&g_partials[i]);
    double wsum = 0.0;
    if (tid < NWSUM) wsum = (double)__ldcg(&g_wsum[tid]);   // NWSUM=128 < 256
    sdbl[tid] = num;
    __syncthreads();
    // reduce num
    #pragma unroll
    for (int off = 128; off > 0; off >>= 1) {
        if (tid < off) sdbl[tid] += sdbl[tid + off];
        __syncthreads();
    }
    double num_tot = sdbl[0];
    __syncthreads();
    sdbl[tid] = wsum;
    __syncthreads();
    #pragma unroll
    for (int off = 128; off > 0; off >>= 1) {
        if (tid < off) sdbl[tid] += sdbl[tid + off];
        __syncthreads();
    }
    if (tid == 0) {
        double den = sdbl[0] * (double)(V_ * C_ * T_);
        out[0] = (float)(num_tot / den);
        g_ticket = 0;   // reset for next graph replay
    }
}

extern "C" void kernel_launch(void* const* d_in, const int* in_sizes, int n_in,
                              void* d_out, int out_size)
{
    const float* pred = (const float*)d_in[0];
    const int*  mask = (const int*)d_in[1];
    const float* vq  = (const float*)d_in[2];
    float* out = (float*)d_out;

    fused_loss_kernel<<<NCTAS, 256>>>(pred, mask, vq, out);
}